// round 5
// baseline (speedup 1.0000x reference)
#include <cuda_runtime.h>
#include <math.h>

#define HID 1024
#define NHEAD 16
#define DHEAD 64
#define RVOC 32
#define SEQ 2048

// ---------------------------------------------------------------------------
// Scratch (no allocations allowed -> __device__ globals)
// ---------------------------------------------------------------------------
__device__ float g_Q[SEQ * HID];
__device__ float g_K[SEQ * HID];
__device__ float g_V[SEQ * HID];
__device__ float g_ctx[SEQ * HID];
__device__ float g_allrel[SEQ * NHEAD * RVOC];   // [q][h][r]

// ---------------------------------------------------------------------------
// SGEMM: C[M,N] = A[M,K] @ B[K,N] + bias[N]   (row-major, M,N mult of 128, K mult of 8)
// 128x128 block tile, BK=8, 256 threads, 8x8 micro-tile
// ---------------------------------------------------------------------------
__global__ __launch_bounds__(256) void sgemm_bias(
    const float* __restrict__ A, const float* __restrict__ B,
    const float* __restrict__ bias, float* __restrict__ C,
    int M, int N, int K)
{
    __shared__ float As[8][128];
    __shared__ float Bs[8][128];

    const int tid  = threadIdx.x;
    const int brow = blockIdx.y * 128;
    const int bcol = blockIdx.x * 128;
    const int trow = (tid >> 4) * 8;     // 0..120
    const int tcol = (tid & 15) * 8;     // 0..120

    // A tile load mapping: 128 rows x 8 cols = 1024 floats, float4 per thread
    const int arow = tid >> 1;           // 0..127
    const int acol = (tid & 1) * 4;      // 0 or 4
    // B tile load mapping: 8 rows x 128 cols
    const int browb = tid >> 5;          // 0..7
    const int bcolb = (tid & 31) * 4;    // 0..124

    float acc[8][8];
    #pragma unroll
    for (int i = 0; i < 8; i++)
        #pragma unroll
        for (int j = 0; j < 8; j++) acc[i][j] = 0.f;

    for (int k0 = 0; k0 < K; k0 += 8) {
        float4 av = *(const float4*)&A[(size_t)(brow + arow) * K + k0 + acol];
        As[acol + 0][arow] = av.x;
        As[acol + 1][arow] = av.y;
        As[acol + 2][arow] = av.z;
        As[acol + 3][arow] = av.w;
        *(float4*)&Bs[browb][bcolb] =
            *(const float4*)&B[(size_t)(k0 + browb) * N + bcol + bcolb];
        __syncthreads();

        #pragma unroll
        for (int kk = 0; kk < 8; kk++) {
            float a[8], b[8];
            *(float4*)&a[0] = *(float4*)&As[kk][trow];
            *(float4*)&a[4] = *(float4*)&As[kk][trow + 4];
            *(float4*)&b[0] = *(float4*)&Bs[kk][tcol];
            *(float4*)&b[4] = *(float4*)&Bs[kk][tcol + 4];
            #pragma unroll
            for (int i = 0; i < 8; i++)
                #pragma unroll
                for (int j = 0; j < 8; j++)
                    acc[i][j] = fmaf(a[i], b[j], acc[i][j]);
        }
        __syncthreads();
    }

    float4 bv0 = *(const float4*)&bias[bcol + tcol];
    float4 bv1 = *(const float4*)&bias[bcol + tcol + 4];
    #pragma unroll
    for (int i = 0; i < 8; i++) {
        int row = brow + trow + i;
        float4 c0 = make_float4(acc[i][0] + bv0.x, acc[i][1] + bv0.y,
                                acc[i][2] + bv0.z, acc[i][3] + bv0.w);
        float4 c1 = make_float4(acc[i][4] + bv1.x, acc[i][5] + bv1.y,
                                acc[i][6] + bv1.z, acc[i][7] + bv1.w);
        *(float4*)&C[(size_t)row * N + bcol + tcol]     = c0;
        *(float4*)&C[(size_t)row * N + bcol + tcol + 4] = c1;
    }
}

// ---------------------------------------------------------------------------
// all_rel[q][h][r] = dot(Q[q, h*64 : h*64+64], rel_emb[r][h][:]) + rel_bias[r][h]
// one block per q, 256 threads, 512 outputs per block
// ---------------------------------------------------------------------------
__global__ __launch_bounds__(256) void rel_kernel(
    const float* __restrict__ rel_emb, const float* __restrict__ rel_bias)
{
    __shared__ float qrow[HID];
    const int q = blockIdx.x;
    const float* Qr = g_Q + (size_t)q * HID;
    for (int i = threadIdx.x; i < HID / 4; i += 256)
        ((float4*)qrow)[i] = ((const float4*)Qr)[i];
    __syncthreads();

    for (int o = threadIdx.x; o < NHEAD * RVOC; o += 256) {
        const int h = o >> 5;        // / RVOC
        const int r = o & 31;        // % RVOC
        const float* e  = rel_emb + ((size_t)r * NHEAD + h) * DHEAD;
        const float* qh = qrow + h * DHEAD;
        float s = 0.f;
        #pragma unroll
        for (int d = 0; d < DHEAD; d += 4) {
            float4 qv = *(const float4*)&qh[d];
            float4 ev = *(const float4*)&e[d];
            s = fmaf(qv.x, ev.x, s);
            s = fmaf(qv.y, ev.y, s);
            s = fmaf(qv.z, ev.z, s);
            s = fmaf(qv.w, ev.w, s);
        }
        g_allrel[(size_t)q * (NHEAD * RVOC) + h * RVOC + r] =
            s + rel_bias[r * NHEAD + h];
    }
}

// ---------------------------------------------------------------------------
// Flash attention per (head, 64-q-row tile).
// 256 threads as 16x16 grid; 4x4 micro-tiles for S and for O.
// smem layout (floats):
//   Qt [64][65]  (dh-major transposed Q tile)      0     .. 4160
//   Kt [64][65]  (dh-major transposed K tile)      4160  .. 8320
//   Vs [64][68]  (k-major V tile)                  8320  .. 12672
//   Ps [64][68]  (q-major probabilities)           12672 .. 17024
//   Rs [64][32]  (rel table rows for this q tile)  17024 .. 19072
// ---------------------------------------------------------------------------
#define ATTN_SMEM_FLOATS 19072
#define ATTN_SMEM_BYTES  (ATTN_SMEM_FLOATS * 4)

__global__ __launch_bounds__(256) void attn_kernel(
    const int* __restrict__ att_mask, const int* __restrict__ rel_ids)
{
    extern __shared__ float sm[];
    float* Qt = sm;            // [64][65]
    float* Kt = sm + 4160;     // [64][65]
    float* Vs = sm + 8320;     // [64][68]
    float* Ps = sm + 12672;    // [64][68]
    float* Rs = sm + 17024;    // [64][32]

    const int h   = blockIdx.y;
    const int q0  = blockIdx.x * 64;
    const int tid = threadIdx.x;
    const int tx  = tid & 15;
    const int ty  = tid >> 4;

    // ---- load Q tile (transposed) + rel rows ----
    {
        const int r0 = tid >> 4;          // 0..15
        const int dg = (tid & 15) * 4;    // 0..60
        #pragma unroll
        for (int rr = r0; rr < 64; rr += 16) {
            float4 v = *(const float4*)&g_Q[(size_t)(q0 + rr) * HID + h * DHEAD + dg];
            Qt[(dg + 0) * 65 + rr] = v.x;
            Qt[(dg + 1) * 65 + rr] = v.y;
            Qt[(dg + 2) * 65 + rr] = v.z;
            Qt[(dg + 3) * 65 + rr] = v.w;
        }
        for (int i = tid; i < 64 * RVOC / 4; i += 256) {
            int rq = i >> 3;
            int c4 = (i & 7) * 4;
            *(float4*)&Rs[rq * RVOC + c4] =
                *(const float4*)&g_allrel[(size_t)(q0 + rq) * (NHEAD * RVOC) + h * RVOC + c4];
        }
    }

    float o_acc[4][4];
    float m_run[4], l_run[4];
    #pragma unroll
    for (int i = 0; i < 4; i++) {
        m_run[i] = -1e30f;
        l_run[i] = 0.f;
        #pragma unroll
        for (int j = 0; j < 4; j++) o_acc[i][j] = 0.f;
    }

    for (int k0 = 0; k0 < SEQ; k0 += 64) {
        __syncthreads();   // protect Kt/Vs/Ps from previous iteration's readers

        // ---- load K (transposed) + V tiles ----
        {
            const int r0 = tid >> 4;
            const int dg = (tid & 15) * 4;
            #pragma unroll
            for (int rr = r0; rr < 64; rr += 16) {
                float4 kv = *(const float4*)&g_K[(size_t)(k0 + rr) * HID + h * DHEAD + dg];
                Kt[(dg + 0) * 65 + rr] = kv.x;
                Kt[(dg + 1) * 65 + rr] = kv.y;
                Kt[(dg + 2) * 65 + rr] = kv.z;
                Kt[(dg + 3) * 65 + rr] = kv.w;
                float4 vv = *(const float4*)&g_V[(size_t)(k0 + rr) * HID + h * DHEAD + dg];
                *(float4*)&Vs[rr * 68 + dg] = vv;
            }
        }
        __syncthreads();

        // ---- S = Q . K^T  (4x4 per thread) ----
        float s[4][4];
        #pragma unroll
        for (int i = 0; i < 4; i++)
            #pragma unroll
            for (int j = 0; j < 4; j++) s[i][j] = 0.f;

        #pragma unroll 8
        for (int kk = 0; kk < 64; kk++) {
            float a0 = Qt[kk * 65 + 4 * ty + 0];
            float a1 = Qt[kk * 65 + 4 * ty + 1];
            float a2 = Qt[kk * 65 + 4 * ty + 2];
            float a3 = Qt[kk * 65 + 4 * ty + 3];
            float b0 = Kt[kk * 65 + 4 * tx + 0];
            float b1 = Kt[kk * 65 + 4 * tx + 1];
            float b2 = Kt[kk * 65 + 4 * tx + 2];
            float b3 = Kt[kk * 65 + 4 * tx + 3];
            s[0][0] = fmaf(a0, b0, s[0][0]); s[0][1] = fmaf(a0, b1, s[0][1]);
            s[0][2] = fmaf(a0, b2, s[0][2]); s[0][3] = fmaf(a0, b3, s[0][3]);
            s[1][0] = fmaf(a1, b0, s[1][0]); s[1][1] = fmaf(a1, b1, s[1][1]);
            s[1][2] = fmaf(a1, b2, s[1][2]); s[1][3] = fmaf(a1, b3, s[1][3]);
            s[2][0] = fmaf(a2, b0, s[2][0]); s[2][1] = fmaf(a2, b1, s[2][1]);
            s[2][2] = fmaf(a2, b2, s[2][2]); s[2][3] = fmaf(a2, b3, s[2][3]);
            s[3][0] = fmaf(a3, b0, s[3][0]); s[3][1] = fmaf(a3, b1, s[3][1]);
            s[3][2] = fmaf(a3, b2, s[3][2]); s[3][3] = fmaf(a3, b3, s[3][3]);
        }

        // ---- + relative scores (gather), scale, mask ----
        #pragma unroll
        for (int i = 0; i < 4; i++) {
            const int qrow = q0 + 4 * ty + i;
            const int4 idv = *(const int4*)&rel_ids[(size_t)qrow * SEQ + k0 + 4 * tx];
            const int4 mv  = *(const int4*)&att_mask[(size_t)qrow * SEQ + k0 + 4 * tx];
            const float* rrow = &Rs[(4 * ty + i) * RVOC];
            s[i][0] = (s[i][0] + rrow[idv.x]) * 0.125f - 10000.f * (1.f - (float)mv.x);
            s[i][1] = (s[i][1] + rrow[idv.y]) * 0.125f - 10000.f * (1.f - (float)mv.y);
            s[i][2] = (s[i][2] + rrow[idv.z]) * 0.125f - 10000.f * (1.f - (float)mv.z);
            s[i][3] = (s[i][3] + rrow[idv.w]) * 0.125f - 10000.f * (1.f - (float)mv.w);
        }

        // ---- online softmax update (row reductions across the 16 tx lanes) ----
        #pragma unroll
        for (int i = 0; i < 4; i++) {
            float tm = fmaxf(fmaxf(s[i][0], s[i][1]), fmaxf(s[i][2], s[i][3]));
            #pragma unroll
            for (int off = 8; off >= 1; off >>= 1)
                tm = fmaxf(tm, __shfl_xor_sync(0xffffffffu, tm, off, 16));
            float nm   = fmaxf(m_run[i], tm);
            float corr = __expf(m_run[i] - nm);
            m_run[i] = nm;
            float rs = 0.f;
            #pragma unroll
            for (int j = 0; j < 4; j++) {
                float p = __expf(s[i][j] - nm);
                s[i][j] = p;
                rs += p;
            }
            #pragma unroll
            for (int off = 8; off >= 1; off >>= 1)
                rs += __shfl_xor_sync(0xffffffffu, rs, off, 16);
            l_run[i] = l_run[i] * corr + rs;
            #pragma unroll
            for (int j = 0; j < 4; j++) o_acc[i][j] *= corr;
        }

        // ---- stage P in smem ----
        #pragma unroll
        for (int i = 0; i < 4; i++)
            *(float4*)&Ps[(4 * ty + i) * 68 + 4 * tx] =
                make_float4(s[i][0], s[i][1], s[i][2], s[i][3]);
        __syncthreads();

        // ---- O += P @ V ----
        #pragma unroll 8
        for (int kk = 0; kk < 64; kk++) {
            float a0 = Ps[(4 * ty + 0) * 68 + kk];
            float a1 = Ps[(4 * ty + 1) * 68 + kk];
            float a2 = Ps[(4 * ty + 2) * 68 + kk];
            float a3 = Ps[(4 * ty + 3) * 68 + kk];
            float4 bv = *(const float4*)&Vs[kk * 68 + 4 * tx];
            o_acc[0][0] = fmaf(a0, bv.x, o_acc[0][0]); o_acc[0][1] = fmaf(a0, bv.y, o_acc[0][1]);
            o_acc[0][2] = fmaf(a0, bv.z, o_acc[0][2]); o_acc[0][3] = fmaf(a0, bv.w, o_acc[0][3]);
            o_acc[1][0] = fmaf(a1, bv.x, o_acc[1][0]); o_acc[1][1] = fmaf(a1, bv.y, o_acc[1][1]);
            o_acc[1][2] = fmaf(a1, bv.z, o_acc[1][2]); o_acc[1][3] = fmaf(a1, bv.w, o_acc[1][3]);
            o_acc[2][0] = fmaf(a2, bv.x, o_acc[2][0]); o_acc[2][1] = fmaf(a2, bv.y, o_acc[2][1]);
            o_acc[2][2] = fmaf(a2, bv.z, o_acc[2][2]); o_acc[2][3] = fmaf(a2, bv.w, o_acc[2][3]);
            o_acc[3][0] = fmaf(a3, bv.x, o_acc[3][0]); o_acc[3][1] = fmaf(a3, bv.y, o_acc[3][1]);
            o_acc[3][2] = fmaf(a3, bv.z, o_acc[3][2]); o_acc[3][3] = fmaf(a3, bv.w, o_acc[3][3]);
        }
    }

    // ---- normalize + write ctx ----
    #pragma unroll
    for (int i = 0; i < 4; i++) {
        float inv = 1.f / l_run[i];
        float4 ov = make_float4(o_acc[i][0] * inv, o_acc[i][1] * inv,
                                o_acc[i][2] * inv, o_acc[i][3] * inv);
        *(float4*)&g_ctx[(size_t)(q0 + 4 * ty + i) * HID + h * DHEAD + 4 * tx] = ov;
    }
}

// ---------------------------------------------------------------------------
// launch
// ---------------------------------------------------------------------------
extern "C" void kernel_launch(void* const* d_in, const int* in_sizes, int n_in,
                              void* d_out, int out_size)
{
    (void)in_sizes; (void)n_in; (void)out_size;
    const float* x        = (const float*)d_in[0];
    const int*   att_mask = (const int*)  d_in[1];
    const int*   rel_ids  = (const int*)  d_in[2];
    const float* Wq       = (const float*)d_in[3];
    const float* bq       = (const float*)d_in[4];
    const float* Wk       = (const float*)d_in[5];
    const float* bk       = (const float*)d_in[6];
    const float* Wv       = (const float*)d_in[7];
    const float* bv       = (const float*)d_in[8];
    const float* rel_emb  = (const float*)d_in[9];
    const float* rel_bias = (const float*)d_in[10];
    const float* Wo       = (const float*)d_in[11];
    const float* bo       = (const float*)d_in[12];
    float* out = (float*)d_out;

    float *pQ, *pK, *pV, *pCtx;
    cudaGetSymbolAddress((void**)&pQ,   g_Q);
    cudaGetSymbolAddress((void**)&pK,   g_K);
    cudaGetSymbolAddress((void**)&pV,   g_V);
    cudaGetSymbolAddress((void**)&pCtx, g_ctx);

    cudaFuncSetAttribute(attn_kernel,
                         cudaFuncAttributeMaxDynamicSharedMemorySize,
                         ATTN_SMEM_BYTES);

    dim3 ggrid(HID / 128, SEQ / 128);
    sgemm_bias<<<ggrid, 256>>>(x, Wq, bq, pQ, SEQ, HID, HID);
    sgemm_bias<<<ggrid, 256>>>(x, Wk, bk, pK, SEQ, HID, HID);
    sgemm_bias<<<ggrid, 256>>>(x, Wv, bv, pV, SEQ, HID, HID);

    rel_kernel<<<SEQ, 256>>>(rel_emb, rel_bias);

    attn_kernel<<<dim3(SEQ / 64, NHEAD), 256, ATTN_SMEM_BYTES>>>(att_mask, rel_ids);

    sgemm_bias<<<ggrid, 256>>>(pCtx, Wo, bo, out, SEQ, HID, HID);
}

// round 6
// speedup vs baseline: 2.6272x; 2.6272x over previous
#include <cuda_runtime.h>
#include <math.h>
#include <stdint.h>

#define HID 1024
#define NHEAD 16
#define DHEAD 64
#define RVOC 32
#define SEQ 2048

// ---------------------------------------------------------------------------
// Scratch (no allocations allowed -> __device__ globals)
// ---------------------------------------------------------------------------
__device__ float g_Q[SEQ * HID];
__device__ float g_K[SEQ * HID];
__device__ float g_V[SEQ * HID];
__device__ float g_ctx[SEQ * HID];

// ---------------------------------------------------------------------------
// helpers: tf32 rounding + m16n8k8 tf32 mma
// ---------------------------------------------------------------------------
__device__ __forceinline__ float tf32r(float x) {
    asm("cvt.rna.tf32.f32 %0, %0;" : "+f"(x));
    return x;
}
__device__ __forceinline__ float4 tf32r4(float4 v) {
    v.x = tf32r(v.x); v.y = tf32r(v.y); v.z = tf32r(v.z); v.w = tf32r(v.w);
    return v;
}
// D = A(16x8,row) * B(8x8,col) + D, fp32 accum
__device__ __forceinline__ void mma_tf32(float* c, const float* a, const float* b) {
    const uint32_t* A = reinterpret_cast<const uint32_t*>(a);
    const uint32_t* B = reinterpret_cast<const uint32_t*>(b);
    asm volatile(
        "mma.sync.aligned.m16n8k8.row.col.f32.tf32.tf32.f32 "
        "{%0,%1,%2,%3}, {%4,%5,%6,%7}, {%8,%9}, {%0,%1,%2,%3};\n"
        : "+f"(c[0]), "+f"(c[1]), "+f"(c[2]), "+f"(c[3])
        : "r"(A[0]), "r"(A[1]), "r"(A[2]), "r"(A[3]), "r"(B[0]), "r"(B[1]));
}

// ---------------------------------------------------------------------------
// tf32 tensor-core GEMM: C[M,N] = A[M,K] @ B[K,N] + bias[N]
// 128x128 block tile, BK=16, 256 threads = 8 warps (4 x 2), warp tile 32x64
// ---------------------------------------------------------------------------
#define SA 20     // As row stride (floats): conflict-free A-fragment LDS
#define SB 136    // Bs row stride (floats): conflict-free B-fragment LDS

__global__ __launch_bounds__(256) void gemm_tf32(
    const float* __restrict__ A, const float* __restrict__ B,
    const float* __restrict__ bias, float* __restrict__ C,
    int M, int N, int K)
{
    __shared__ float As[128 * SA];
    __shared__ float Bs[16 * SB];

    const int tid  = threadIdx.x;
    const int lane = tid & 31;
    const int wid  = tid >> 5;
    const int g    = lane >> 2;   // groupID
    const int t    = lane & 3;    // threadID_in_group
    const int wm   = (wid & 3) * 32;
    const int wn   = (wid >> 2) * 64;
    const int brow = blockIdx.y * 128;
    const int bcol = blockIdx.x * 128;

    // global->smem mappings
    const int arow = tid >> 2;          // 0..63 (and +64)
    const int akc  = (tid & 3) * 4;
    const int br   = tid >> 5;          // 0..7 (and +8)
    const int bnc  = (tid & 31) * 4;

    float acc[2][8][4];
    #pragma unroll
    for (int mt = 0; mt < 2; mt++)
        #pragma unroll
        for (int nt = 0; nt < 8; nt++)
            #pragma unroll
            for (int i = 0; i < 4; i++) acc[mt][nt][i] = 0.f;

    float4 pa0 = *(const float4*)&A[(size_t)(brow + arow)      * K + akc];
    float4 pa1 = *(const float4*)&A[(size_t)(brow + arow + 64) * K + akc];
    float4 pb0 = *(const float4*)&B[(size_t)(br)     * N + bcol + bnc];
    float4 pb1 = *(const float4*)&B[(size_t)(br + 8) * N + bcol + bnc];

    for (int k0 = 0; k0 < K; k0 += 16) {
        *(float4*)&As[(arow)      * SA + akc] = tf32r4(pa0);
        *(float4*)&As[(arow + 64) * SA + akc] = tf32r4(pa1);
        *(float4*)&Bs[(br)     * SB + bnc]    = tf32r4(pb0);
        *(float4*)&Bs[(br + 8) * SB + bnc]    = tf32r4(pb1);
        __syncthreads();

        int k1 = k0 + 16;
        if (k1 < K) {
            pa0 = *(const float4*)&A[(size_t)(brow + arow)      * K + k1 + akc];
            pa1 = *(const float4*)&A[(size_t)(brow + arow + 64) * K + k1 + akc];
            pb0 = *(const float4*)&B[(size_t)(k1 + br)     * N + bcol + bnc];
            pb1 = *(const float4*)&B[(size_t)(k1 + br + 8) * N + bcol + bnc];
        }

        #pragma unroll
        for (int ks = 0; ks < 16; ks += 8) {
            float a[2][4], b[8][2];
            #pragma unroll
            for (int mt = 0; mt < 2; mt++) {
                a[mt][0] = As[(wm + mt * 16 + g)     * SA + ks + t];
                a[mt][1] = As[(wm + mt * 16 + g + 8) * SA + ks + t];
                a[mt][2] = As[(wm + mt * 16 + g)     * SA + ks + t + 4];
                a[mt][3] = As[(wm + mt * 16 + g + 8) * SA + ks + t + 4];
            }
            #pragma unroll
            for (int nt = 0; nt < 8; nt++) {
                b[nt][0] = Bs[(ks + t)     * SB + wn + nt * 8 + g];
                b[nt][1] = Bs[(ks + t + 4) * SB + wn + nt * 8 + g];
            }
            #pragma unroll
            for (int mt = 0; mt < 2; mt++)
                #pragma unroll
                for (int nt = 0; nt < 8; nt++)
                    mma_tf32(acc[mt][nt], a[mt], b[nt]);
        }
        __syncthreads();
    }

    // epilogue: bias + store (C-fragment layout)
    #pragma unroll
    for (int nt = 0; nt < 8; nt++) {
        const int col = bcol + wn + nt * 8 + 2 * t;
        float2 bv = *(const float2*)&bias[col];
        #pragma unroll
        for (int mt = 0; mt < 2; mt++) {
            int r0 = brow + wm + mt * 16 + g;
            float2 c01 = make_float2(acc[mt][nt][0] + bv.x, acc[mt][nt][1] + bv.y);
            float2 c23 = make_float2(acc[mt][nt][2] + bv.x, acc[mt][nt][3] + bv.y);
            *(float2*)&C[(size_t)r0 * N + col]       = c01;
            *(float2*)&C[(size_t)(r0 + 8) * N + col] = c23;
        }
    }
}

// ---------------------------------------------------------------------------
// Flash attention, tf32 tensor cores. Block = (64 q rows, 1 head), 128 thr,
// 4 warps; warp tile = 16q x 64keys (S) and 16q x 64d (O).
// Rel scores computed in-block: Rs[64q][32r] = Qtile @ rel_emb[.,h,.]^T + bias
// smem (floats): Qs[64][68] | Ks[64][68] | Vs[64][72] | Ps[64][76] | Rs[64][32]
//   (Es[64][40] for rel_emb aliases the Ps region during the prologue)
// ---------------------------------------------------------------------------
#define SQ 68
#define SK 68
#define SV 72
#define SP 76
#define SE 40
#define OFF_Q 0
#define OFF_K 4352
#define OFF_V 8704
#define OFF_P 13312
#define OFF_R 18176
#define ATTN_SMEM_FLOATS 20224
#define ATTN_SMEM_BYTES  (ATTN_SMEM_FLOATS * 4)

__global__ __launch_bounds__(128) void attn_kernel(
    const int* __restrict__ att_mask, const int* __restrict__ rel_ids,
    const float* __restrict__ rel_emb, const float* __restrict__ rel_bias)
{
    extern __shared__ float sm[];
    float* Qs = sm + OFF_Q;
    float* Ks = sm + OFF_K;
    float* Vs = sm + OFF_V;
    float* Ps = sm + OFF_P;
    float* Es = sm + OFF_P;   // prologue alias
    float* Rs = sm + OFF_R;

    const int h    = blockIdx.y;
    const int q0   = blockIdx.x * 64;
    const int tid  = threadIdx.x;
    const int lane = tid & 31;
    const int wid  = tid >> 5;
    const int g    = lane >> 2;
    const int t    = lane & 3;
    const int wq   = wid * 16;

    // ---- prologue: stage Q (tf32) and rel_emb[.,h,.] transposed ----
    #pragma unroll
    for (int i = tid; i < 64 * 16; i += 128) {          // Q: 1024 float4
        int row = i >> 4, dc = (i & 15) * 4;
        float4 v = *(const float4*)&g_Q[(size_t)(q0 + row) * HID + h * DHEAD + dc];
        *(float4*)&Qs[row * SQ + dc] = tf32r4(v);
    }
    #pragma unroll
    for (int i = tid; i < 32 * 16; i += 128) {          // rel_emb: 512 float4
        int r = i >> 4, dc = (i & 15) * 4;
        float4 v = *(const float4*)&rel_emb[((size_t)r * NHEAD + h) * DHEAD + dc];
        Es[(dc + 0) * SE + r] = tf32r(v.x);
        Es[(dc + 1) * SE + r] = tf32r(v.y);
        Es[(dc + 2) * SE + r] = tf32r(v.z);
        Es[(dc + 3) * SE + r] = tf32r(v.w);
    }
    __syncthreads();

    // ---- hoist Q A-fragments (constant across all k-tiles) ----
    float qa[8][4];
    #pragma unroll
    for (int ks = 0; ks < 8; ks++) {
        qa[ks][0] = Qs[(wq + g)     * SQ + ks * 8 + t];
        qa[ks][1] = Qs[(wq + g + 8) * SQ + ks * 8 + t];
        qa[ks][2] = Qs[(wq + g)     * SQ + ks * 8 + t + 4];
        qa[ks][3] = Qs[(wq + g + 8) * SQ + ks * 8 + t + 4];
    }

    // ---- rel scores: Rs = Qtile @ E + bias (tiny mma GEMM) ----
    {
        float rc[4][4];
        #pragma unroll
        for (int nt = 0; nt < 4; nt++)
            #pragma unroll
            for (int i = 0; i < 4; i++) rc[nt][i] = 0.f;
        #pragma unroll
        for (int ks = 0; ks < 8; ks++)
            #pragma unroll
            for (int nt = 0; nt < 4; nt++) {
                float b[2];
                b[0] = Es[(ks * 8 + t)     * SE + nt * 8 + g];
                b[1] = Es[(ks * 8 + t + 4) * SE + nt * 8 + g];
                mma_tf32(rc[nt], qa[ks], b);
            }
        #pragma unroll
        for (int nt = 0; nt < 4; nt++) {
            int r = nt * 8 + 2 * t;
            float bx = rel_bias[(size_t)r * NHEAD + h];
            float by = rel_bias[(size_t)(r + 1) * NHEAD + h];
            Rs[(wq + g)     * 32 + r]     = rc[nt][0] + bx;
            Rs[(wq + g)     * 32 + r + 1] = rc[nt][1] + by;
            Rs[(wq + g + 8) * 32 + r]     = rc[nt][2] + bx;
            Rs[(wq + g + 8) * 32 + r + 1] = rc[nt][3] + by;
        }
        __syncwarp();
    }

    float oacc[8][4];
    #pragma unroll
    for (int nt = 0; nt < 8; nt++)
        #pragma unroll
        for (int i = 0; i < 4; i++) oacc[nt][i] = 0.f;
    float m0 = -1e30f, m1 = -1e30f, l0 = 0.f, l1 = 0.f;

    const int qr0 = q0 + wq + g;      // global q row for c0/c1
    const int qr1 = qr0 + 8;          // for c2/c3
    const float* rrow0 = &Rs[(wq + g) * 32];
    const float* rrow1 = &Rs[(wq + g + 8) * 32];

    for (int k0 = 0; k0 < SEQ; k0 += 64) {
        __syncthreads();   // protect Ks/Vs from previous iteration's readers

        #pragma unroll
        for (int i = tid; i < 64 * 16; i += 128) {
            int row = i >> 4, dc = (i & 15) * 4;
            float4 kv = *(const float4*)&g_K[(size_t)(k0 + row) * HID + h * DHEAD + dc];
            *(float4*)&Ks[row * SK + dc] = tf32r4(kv);
            float4 vv = *(const float4*)&g_V[(size_t)(k0 + row) * HID + h * DHEAD + dc];
            *(float4*)&Vs[row * SV + dc] = tf32r4(vv);
        }
        __syncthreads();

        // ---- S = Q @ K^T ----
        float s[8][4];
        #pragma unroll
        for (int nt = 0; nt < 8; nt++)
            #pragma unroll
            for (int i = 0; i < 4; i++) s[nt][i] = 0.f;
        #pragma unroll
        for (int ks = 0; ks < 8; ks++)
            #pragma unroll
            for (int nt = 0; nt < 8; nt++) {
                float b[2];
                b[0] = Ks[(nt * 8 + g) * SK + ks * 8 + t];
                b[1] = Ks[(nt * 8 + g) * SK + ks * 8 + t + 4];
                mma_tf32(s[nt], qa[ks], b);
            }

        // ---- + rel gather, scale, mask ----
        #pragma unroll
        for (int nt = 0; nt < 8; nt++) {
            const int col = k0 + nt * 8 + 2 * t;
            int2 id0 = *(const int2*)&rel_ids[(size_t)qr0 * SEQ + col];
            int2 id1 = *(const int2*)&rel_ids[(size_t)qr1 * SEQ + col];
            int2 mk0 = *(const int2*)&att_mask[(size_t)qr0 * SEQ + col];
            int2 mk1 = *(const int2*)&att_mask[(size_t)qr1 * SEQ + col];
            s[nt][0] = (s[nt][0] + rrow0[id0.x]) * 0.125f - 10000.f * (1.f - (float)mk0.x);
            s[nt][1] = (s[nt][1] + rrow0[id0.y]) * 0.125f - 10000.f * (1.f - (float)mk0.y);
            s[nt][2] = (s[nt][2] + rrow1[id1.x]) * 0.125f - 10000.f * (1.f - (float)mk1.x);
            s[nt][3] = (s[nt][3] + rrow1[id1.y]) * 0.125f - 10000.f * (1.f - (float)mk1.y);
        }

        // ---- online softmax (rows g and g+8; reduce over 4 lanes of quad) ----
        float tm0 = -1e30f, tm1 = -1e30f;
        #pragma unroll
        for (int nt = 0; nt < 8; nt++) {
            tm0 = fmaxf(tm0, fmaxf(s[nt][0], s[nt][1]));
            tm1 = fmaxf(tm1, fmaxf(s[nt][2], s[nt][3]));
        }
        tm0 = fmaxf(tm0, __shfl_xor_sync(0xffffffffu, tm0, 1, 4));
        tm0 = fmaxf(tm0, __shfl_xor_sync(0xffffffffu, tm0, 2, 4));
        tm1 = fmaxf(tm1, __shfl_xor_sync(0xffffffffu, tm1, 1, 4));
        tm1 = fmaxf(tm1, __shfl_xor_sync(0xffffffffu, tm1, 2, 4));
        float nm0 = fmaxf(m0, tm0), nm1 = fmaxf(m1, tm1);
        float c0 = __expf(m0 - nm0), c1 = __expf(m1 - nm1);
        m0 = nm0; m1 = nm1;
        float rs0 = 0.f, rs1 = 0.f;
        #pragma unroll
        for (int nt = 0; nt < 8; nt++) {
            s[nt][0] = __expf(s[nt][0] - nm0);
            s[nt][1] = __expf(s[nt][1] - nm0);
            s[nt][2] = __expf(s[nt][2] - nm1);
            s[nt][3] = __expf(s[nt][3] - nm1);
            rs0 += s[nt][0] + s[nt][1];
            rs1 += s[nt][2] + s[nt][3];
        }
        rs0 += __shfl_xor_sync(0xffffffffu, rs0, 1, 4);
        rs0 += __shfl_xor_sync(0xffffffffu, rs0, 2, 4);
        rs1 += __shfl_xor_sync(0xffffffffu, rs1, 1, 4);
        rs1 += __shfl_xor_sync(0xffffffffu, rs1, 2, 4);
        l0 = l0 * c0 + rs0;
        l1 = l1 * c1 + rs1;
        #pragma unroll
        for (int nt = 0; nt < 8; nt++) {
            oacc[nt][0] *= c0; oacc[nt][1] *= c0;
            oacc[nt][2] *= c1; oacc[nt][3] *= c1;
        }

        // ---- stage P (tf32) — each warp writes only its own 16 q-rows ----
        #pragma unroll
        for (int nt = 0; nt < 8; nt++) {
            int col = nt * 8 + 2 * t;
            *(float2*)&Ps[(wq + g)     * SP + col] =
                make_float2(tf32r(s[nt][0]), tf32r(s[nt][1]));
            *(float2*)&Ps[(wq + g + 8) * SP + col] =
                make_float2(tf32r(s[nt][2]), tf32r(s[nt][3]));
        }
        __syncwarp();

        // ---- O += P @ V ----
        #pragma unroll
        for (int ks = 0; ks < 8; ks++) {
            float pa[4];
            pa[0] = Ps[(wq + g)     * SP + ks * 8 + t];
            pa[1] = Ps[(wq + g + 8) * SP + ks * 8 + t];
            pa[2] = Ps[(wq + g)     * SP + ks * 8 + t + 4];
            pa[3] = Ps[(wq + g + 8) * SP + ks * 8 + t + 4];
            #pragma unroll
            for (int nt = 0; nt < 8; nt++) {
                float b[2];
                b[0] = Vs[(ks * 8 + t)     * SV + nt * 8 + g];
                b[1] = Vs[(ks * 8 + t + 4) * SV + nt * 8 + g];
                mma_tf32(oacc[nt], pa, b);
            }
        }
    }

    // ---- normalize + write ctx ----
    float inv0 = 1.f / l0, inv1 = 1.f / l1;
    #pragma unroll
    for (int nt = 0; nt < 8; nt++) {
        int d = h * DHEAD + nt * 8 + 2 * t;
        *(float2*)&g_ctx[(size_t)qr0 * HID + d] =
            make_float2(oacc[nt][0] * inv0, oacc[nt][1] * inv0);
        *(float2*)&g_ctx[(size_t)qr1 * HID + d] =
            make_float2(oacc[nt][2] * inv1, oacc[nt][3] * inv1);
    }
}

// ---------------------------------------------------------------------------
// launch
// ---------------------------------------------------------------------------
extern "C" void kernel_launch(void* const* d_in, const int* in_sizes, int n_in,
                              void* d_out, int out_size)
{
    (void)in_sizes; (void)n_in; (void)out_size;
    const float* x        = (const float*)d_in[0];
    const int*   att_mask = (const int*)  d_in[1];
    const int*   rel_ids  = (const int*)  d_in[2];
    const float* Wq       = (const float*)d_in[3];
    const float* bq       = (const float*)d_in[4];
    const float* Wk       = (const float*)d_in[5];
    const float* bk       = (const float*)d_in[6];
    const float* Wv       = (const float*)d_in[7];
    const float* bv       = (const float*)d_in[8];
    const float* rel_emb  = (const float*)d_in[9];
    const float* rel_bias = (const float*)d_in[10];
    const float* Wo       = (const float*)d_in[11];
    const float* bo       = (const float*)d_in[12];
    float* out = (float*)d_out;

    float *pQ, *pK, *pV, *pCtx;
    cudaGetSymbolAddress((void**)&pQ,   g_Q);
    cudaGetSymbolAddress((void**)&pK,   g_K);
    cudaGetSymbolAddress((void**)&pV,   g_V);
    cudaGetSymbolAddress((void**)&pCtx, g_ctx);

    cudaFuncSetAttribute(attn_kernel,
                         cudaFuncAttributeMaxDynamicSharedMemorySize,
                         ATTN_SMEM_BYTES);

    dim3 ggrid(HID / 128, SEQ / 128);
    gemm_tf32<<<ggrid, 256>>>(x, Wq, bq, pQ, SEQ, HID, HID);
    gemm_tf32<<<ggrid, 256>>>(x, Wk, bk, pK, SEQ, HID, HID);
    gemm_tf32<<<ggrid, 256>>>(x, Wv, bv, pV, SEQ, HID, HID);

    attn_kernel<<<dim3(SEQ / 64, NHEAD), 128, ATTN_SMEM_BYTES>>>(
        att_mask, rel_ids, rel_emb, rel_bias);

    gemm_tf32<<<ggrid, 256>>>(pCtx, Wo, bo, out, SEQ, HID, HID);
}